// round 2
// baseline (speedup 1.0000x reference)
#include <cuda_runtime.h>
#include <cstdint>

// DAS beamform: out[b,z,x,k] = sum_c lerp(rf[b,c,:,k], sample_index(b,c,pixel))
// Shapes: rf [2,128,2048,4] f32 (8 MB, fits L2), g [2,256,256,3], pr [2,128,3], p [2,4]
// Strategy: block = 1024 pixels of one batch, loop 128 channels.
//   - cp.async double-buffer each channel's 32KB row into SMEM (coalesced L2 reads)
//   - per-thread random gather of 2 adjacent float4 rows via LDS.128 + lerp
//   - K=4 accumulator in registers, single coalesced float4 store at end.

#define NC      128
#define NS      2048
#define NPIX    65536          // pixels per batch (Nz*Nx)
#define THREADS 1024
#define TILES_PER_BATCH 64     // 64 * 1024 = 65536
#define GRID    128            // 2 batches * 64 tiles

// dynamic smem: 2 channel buffers (8192 floats each) + pr cache (384 floats)
#define SMEM_FLOATS (2 * NS * 4 + NC * 3)
#define SMEM_BYTES  (SMEM_FLOATS * 4)

__device__ __forceinline__ uint32_t smem_u32(const void* p) {
    uint32_t a;
    asm("{ .reg .u64 t; cvta.to.shared.u64 t, %1; cvt.u32.u64 %0, t; }"
        : "=r"(a) : "l"(p));
    return a;
}

__device__ __forceinline__ void cp_async16(uint32_t dst, const void* src) {
    asm volatile("cp.async.cg.shared.global [%0], [%1], 16;" :: "r"(dst), "l"(src));
}

__global__ __launch_bounds__(THREADS, 1)
void das_kernel(const float* __restrict__ rf,
                const float* __restrict__ g,
                const float* __restrict__ pr,
                const float* __restrict__ p,
                float* __restrict__ out)
{
    extern __shared__ float smem[];
    float* buf0 = smem;                 // 8192 floats = 32 KB
    float* buf1 = smem + NS * 4;        // 8192 floats
    float* spr  = smem + 2 * NS * 4;    // 384 floats

    const int tid  = threadIdx.x;
    const int b    = blockIdx.x / TILES_PER_BATCH;
    const int tile = blockIdx.x % TILES_PER_BATCH;
    const int pix  = tile * THREADS + tid;          // [0, 65536)

    // cache receiver positions for this batch
    if (tid < NC * 3) spr[tid] = pr[b * NC * 3 + tid];

    // acquisition params (broadcast loads, L2/L1 cached)
    const float c0 = p[b * 4 + 0];
    const float fs = p[b * 4 + 1];
    const float t0 = p[b * 4 + 2];
    const float scale = fs / c0;              // samples per meter
    // reference: s = fs*(t0 + d_rx + d_tx)/c0
    const float gx = g[((size_t)b * NPIX + pix) * 3 + 0];
    const float gy = g[((size_t)b * NPIX + pix) * 3 + 1];
    const float gz = g[((size_t)b * NPIX + pix) * 3 + 2];
    const float sbase = scale * (t0 + gz);    // t0 + d_tx term

    const float4* rf4 = reinterpret_cast<const float4*>(rf) + (size_t)b * NC * NS;

    const uint32_t a0 = smem_u32(buf0);
    const uint32_t a1 = smem_u32(buf1);

    // --- fill helper: channel c -> buffer 'which' (each thread copies 2 float4) ---
    auto fill = [&](int c, int which) {
        const float4* src = rf4 + (size_t)c * NS;
        uint32_t dst = which ? a1 : a0;
        cp_async16(dst + (uint32_t)tid * 16u,            src + tid);
        cp_async16(dst + (uint32_t)(tid + 1024) * 16u,   src + tid + 1024);
        asm volatile("cp.async.commit_group;");
    };

    // prologue: channels 0 and 1 in flight
    fill(0, 0);
    fill(1, 1);

    float4 acc = make_float4(0.f, 0.f, 0.f, 0.f);

    #pragma unroll 1
    for (int c = 0; c < NC; c++) {
        if (c < NC - 1) { asm volatile("cp.async.wait_group 1;"); }
        else            { asm volatile("cp.async.wait_group 0;"); }
        __syncthreads();   // buffer[c&1] ready; also orders spr on first iter

        const float prx = spr[c * 3 + 0];
        const float pry = spr[c * 3 + 1];
        const float prz = spr[c * 3 + 2];

        const float dx = gx - prx;
        const float dy = gy - pry;
        const float dz = gz - prz;
        const float dd = fmaf(dx, dx, fmaf(dy, dy, dz * dz));
        float d;
        asm("sqrt.approx.f32 %0, %1;" : "=f"(d) : "f"(dd));

        float s = fmaf(scale, d, sbase);
        s = fminf(fmaxf(s, 0.0f), 2047.0f);
        int i0 = (int)s;                 // s >= 0 -> truncation == floor
        i0 = min(i0, NS - 2);
        const float w  = s - (float)i0;
        const float w0 = 1.0f - w;

        const float4* bp = reinterpret_cast<const float4*>((c & 1) ? buf1 : buf0);
        const float4 y0 = bp[i0];
        const float4 y1 = bp[i0 + 1];

        acc.x = fmaf(w0, y0.x, fmaf(w, y1.x, acc.x));
        acc.y = fmaf(w0, y0.y, fmaf(w, y1.y, acc.y));
        acc.z = fmaf(w0, y0.z, fmaf(w, y1.z, acc.z));
        acc.w = fmaf(w0, y0.w, fmaf(w, y1.w, acc.w));

        __syncthreads();   // everyone done reading buffer[c&1]
        if (c + 2 < NC) fill(c + 2, c & 1);
    }

    float4* out4 = reinterpret_cast<float4*>(out);
    out4[(size_t)b * NPIX + pix] = acc;
}

extern "C" void kernel_launch(void* const* d_in, const int* in_sizes, int n_in,
                              void* d_out, int out_size)
{
    const float* rf = (const float*)d_in[0];
    const float* g  = (const float*)d_in[1];
    const float* pr = (const float*)d_in[2];
    const float* p  = (const float*)d_in[3];
    float* out = (float*)d_out;

    // > 48 KB dynamic smem needs opt-in (idempotent; executes immediately, not captured)
    cudaFuncSetAttribute(das_kernel, cudaFuncAttributeMaxDynamicSharedMemorySize, SMEM_BYTES);

    das_kernel<<<GRID, THREADS, SMEM_BYTES>>>(rf, g, pr, p, out);
}

// round 3
// speedup vs baseline: 1.2340x; 1.2340x over previous
#include <cuda_runtime.h>
#include <cstdint>

// DAS beamform, round 3: 148 blocks (2 batches x 74 tiles, 886 px/block),
// 6-buffer cp.async ring, 2 channels per iteration, ONE barrier per iteration.

#define NC      128
#define NS      2048
#define NPIX    65536
#define THREADS 1024
#define PX_PER_BLOCK 886          // 74 * 886 = 65564 >= 65536
#define TILES_PER_BATCH 74
#define GRID    (2 * TILES_PER_BATCH)   // 148 = #SMs (GB300 has 152; 148 full wave)

#define BUF_FLOATS (NS * 4)       // 8192 floats = 32 KB per channel buffer
#define SMEM_FLOATS (6 * BUF_FLOATS + NC * 3)
#define SMEM_BYTES  (SMEM_FLOATS * 4)

__device__ __forceinline__ uint32_t smem_u32(const void* p) {
    uint32_t a;
    asm("{ .reg .u64 t; cvta.to.shared.u64 t, %1; cvt.u32.u64 %0, t; }"
        : "=r"(a) : "l"(p));
    return a;
}

__device__ __forceinline__ void cp_async16(uint32_t dst, const void* src) {
    asm volatile("cp.async.cg.shared.global [%0], [%1], 16;" :: "r"(dst), "l"(src));
}

__global__ __launch_bounds__(THREADS, 1)
void das_kernel(const float* __restrict__ rf,
                const float* __restrict__ g,
                const float* __restrict__ pr,
                const float* __restrict__ p,
                float* __restrict__ out)
{
    extern __shared__ float smem[];
    float* spr = smem + 6 * BUF_FLOATS;   // 384 floats

    const int tid  = threadIdx.x;
    const int b    = blockIdx.x / TILES_PER_BATCH;
    const int tile = blockIdx.x % TILES_PER_BATCH;
    const int pix0 = tile * PX_PER_BLOCK + tid;
    const bool active = (tid < PX_PER_BLOCK) && (pix0 < NPIX);
    const int pix  = active ? pix0 : 0;   // clamp for safe loads

    if (tid < NC * 3) spr[tid] = pr[b * NC * 3 + tid];

    const float c0 = p[b * 4 + 0];
    const float fs = p[b * 4 + 1];
    const float t0 = p[b * 4 + 2];
    const float scale = fs / c0;
    const float gx = g[((size_t)b * NPIX + pix) * 3 + 0];
    const float gy = g[((size_t)b * NPIX + pix) * 3 + 1];
    const float gz = g[((size_t)b * NPIX + pix) * 3 + 2];
    const float sbase = scale * (t0 + gz);

    const float4* rf4 = reinterpret_cast<const float4*>(rf) + (size_t)b * NC * NS;
    const uint32_t smem_base = smem_u32(smem);

    // fill channel c into ring buffer slot 'slot' (each thread copies 2 float4)
    auto fill = [&](int c, int slot) {
        const float4* src = rf4 + (size_t)c * NS;
        uint32_t dst = smem_base + (uint32_t)slot * (BUF_FLOATS * 4);
        cp_async16(dst + (uint32_t)tid * 16u,          src + tid);
        cp_async16(dst + (uint32_t)(tid + 1024) * 16u, src + tid + 1024);
        asm volatile("cp.async.commit_group;");
    };

    // prologue: channels 0..3 in ring slots 0..3 (pairs 0 and 1)
    fill(0, 0); fill(1, 1); fill(2, 2); fill(3, 3);

    float4 accA = make_float4(0.f, 0.f, 0.f, 0.f);
    float4 accB = make_float4(0.f, 0.f, 0.f, 0.f);

    int pairIdx = 0;   // which buffer pair {0,1,2} holds channels c, c+1

    #pragma unroll 1
    for (int c = 0; c < NC; c += 2) {
        if (c + 2 < NC) { asm volatile("cp.async.wait_group 2;"); }
        else            { asm volatile("cp.async.wait_group 0;"); }
        __syncthreads();  // publishes fills for c,c+1; protects reuse of the pair filled below

        const float paxx = spr[c * 3 + 0], paxy = spr[c * 3 + 1], paxz = spr[c * 3 + 2];
        const float pbxx = spr[c * 3 + 3], pbxy = spr[c * 3 + 4], pbxz = spr[c * 3 + 5];

        // channel c
        float dax = gx - paxx, day = gy - paxy, daz = gz - paxz;
        float dda = fmaf(dax, dax, fmaf(day, day, daz * daz));
        float da; asm("sqrt.approx.f32 %0, %1;" : "=f"(da) : "f"(dda));
        float sa = fmaf(scale, da, sbase);
        sa = fminf(fmaxf(sa, 0.0f), 2047.0f);
        int ia = min((int)sa, NS - 2);
        const float wa = sa - (float)ia, wa0 = 1.0f - wa;

        // channel c+1
        float dbx = gx - pbxx, dby = gy - pbxy, dbz = gz - pbxz;
        float ddb = fmaf(dbx, dbx, fmaf(dby, dby, dbz * dbz));
        float db; asm("sqrt.approx.f32 %0, %1;" : "=f"(db) : "f"(ddb));
        float sb = fmaf(scale, db, sbase);
        sb = fminf(fmaxf(sb, 0.0f), 2047.0f);
        int ib = min((int)sb, NS - 2);
        const float wb = sb - (float)ib, wb0 = 1.0f - wb;

        const float4* bufA = reinterpret_cast<const float4*>(smem + (2 * pairIdx)     * BUF_FLOATS);
        const float4* bufB = reinterpret_cast<const float4*>(smem + (2 * pairIdx + 1) * BUF_FLOATS);

        if (active) {
            const float4 a0 = bufA[ia];
            const float4 a1 = bufA[ia + 1];
            const float4 b0 = bufB[ib];
            const float4 b1 = bufB[ib + 1];

            accA.x = fmaf(wa0, a0.x, fmaf(wa, a1.x, accA.x));
            accA.y = fmaf(wa0, a0.y, fmaf(wa, a1.y, accA.y));
            accA.z = fmaf(wa0, a0.z, fmaf(wa, a1.z, accA.z));
            accA.w = fmaf(wa0, a0.w, fmaf(wa, a1.w, accA.w));

            accB.x = fmaf(wb0, b0.x, fmaf(wb, b1.x, accB.x));
            accB.y = fmaf(wb0, b0.y, fmaf(wb, b1.y, accB.y));
            accB.z = fmaf(wb0, b0.z, fmaf(wb, b1.z, accB.z));
            accB.w = fmaf(wb0, b0.w, fmaf(wb, b1.w, accB.w));
        }

        // prefetch channels c+4, c+5 into the pair two steps ahead.
        // Safe: that pair was last read at iter c-2; this iteration's barrier
        // guarantees all threads finished those reads.
        if (c + 4 < NC) {
            int fp = pairIdx + 2; if (fp >= 3) fp -= 3;
            fill(c + 4, 2 * fp);
            fill(c + 5, 2 * fp + 1);
        }
        pairIdx = (pairIdx + 1 == 3) ? 0 : pairIdx + 1;
    }

    if (active) {
        float4 r;
        r.x = accA.x + accB.x;
        r.y = accA.y + accB.y;
        r.z = accA.z + accB.z;
        r.w = accA.w + accB.w;
        reinterpret_cast<float4*>(out)[(size_t)b * NPIX + pix0] = r;
    }
}

extern "C" void kernel_launch(void* const* d_in, const int* in_sizes, int n_in,
                              void* d_out, int out_size)
{
    const float* rf = (const float*)d_in[0];
    const float* g  = (const float*)d_in[1];
    const float* pr = (const float*)d_in[2];
    const float* p  = (const float*)d_in[3];
    float* out = (float*)d_out;

    cudaFuncSetAttribute(das_kernel, cudaFuncAttributeMaxDynamicSharedMemorySize, SMEM_BYTES);
    das_kernel<<<GRID, THREADS, SMEM_BYTES>>>(rf, g, pr, p, out);
}

// round 7
// speedup vs baseline: 1.7660x; 1.4311x over previous
#include <cuda_runtime.h>
#include <cuda_fp16.h>
#include <cstdint>

// DAS beamform, round 4: fp16 staging.
//   Kernel 1: convert rf f32 -> fp16 into __device__ scratch (8MB -> 4MB).
//   Kernel 2: per-block 1024 px, 6x16KB cp.async ring of fp16 channel rows,
//             gather 2x LDS.64 per channel-pixel, lerp + accumulate in f32.

#define NC      128
#define NS      2048
#define NPIX    65536
#define THREADS 1024
#define PX_PER_BLOCK 886
#define TILES_PER_BATCH 74
#define GRID    (2 * TILES_PER_BATCH)   // 148

#define BUF_BYTES  (NS * 8)             // 2048 rows x 4 half = 16 KB
#define SMEM_BYTES (6 * BUF_BYTES + NC * 3 * 4)

// fp16 copy of rf: [B, Nc, Ns, K] halves = 4 MB (module scratch, allowed)
__device__ __align__(16) __half RF16[2 * NC * NS * 4];

__global__ __launch_bounds__(256)
void conv_kernel(const float4* __restrict__ rf4)
{
    // one thread: 2 float4 (32B) -> 1 uint4 of 8 halves (16B)
    const int idx = blockIdx.x * blockDim.x + threadIdx.x;   // 0 .. 262143
    const float4 a = rf4[2 * idx];
    const float4 b = rf4[2 * idx + 1];
    __half2 h0 = __float22half2_rn(make_float2(a.x, a.y));
    __half2 h1 = __float22half2_rn(make_float2(a.z, a.w));
    __half2 h2 = __float22half2_rn(make_float2(b.x, b.y));
    __half2 h3 = __float22half2_rn(make_float2(b.z, b.w));
    uint4 o;
    o.x = *reinterpret_cast<uint32_t*>(&h0);
    o.y = *reinterpret_cast<uint32_t*>(&h1);
    o.z = *reinterpret_cast<uint32_t*>(&h2);
    o.w = *reinterpret_cast<uint32_t*>(&h3);
    reinterpret_cast<uint4*>(RF16)[idx] = o;
}

__device__ __forceinline__ uint32_t smem_u32(const void* p) {
    uint32_t a;
    asm("{ .reg .u64 t; cvta.to.shared.u64 t, %1; cvt.u32.u64 %0, t; }"
        : "=r"(a) : "l"(p));
    return a;
}

__device__ __forceinline__ void cp_async16(uint32_t dst, const void* src) {
    asm volatile("cp.async.cg.shared.global [%0], [%1], 16;" :: "r"(dst), "l"(src));
}

__global__ __launch_bounds__(THREADS, 1)
void das_kernel(const float* __restrict__ g,
                const float* __restrict__ pr,
                const float* __restrict__ p,
                float* __restrict__ out)
{
    extern __shared__ float smem[];
    float* spr = smem + 6 * (BUF_BYTES / 4);   // 384 floats

    const int tid  = threadIdx.x;
    const int b    = blockIdx.x / TILES_PER_BATCH;
    const int tile = blockIdx.x % TILES_PER_BATCH;
    const int pix0 = tile * PX_PER_BLOCK + tid;
    const bool active = (tid < PX_PER_BLOCK) && (pix0 < NPIX);
    const int pix  = active ? pix0 : 0;

    if (tid < NC * 3) spr[tid] = pr[b * NC * 3 + tid];

    const float c0 = p[b * 4 + 0];
    const float fs = p[b * 4 + 1];
    const float t0 = p[b * 4 + 2];
    const float scale = fs / c0;
    const float gx = g[((size_t)b * NPIX + pix) * 3 + 0];
    const float gy = g[((size_t)b * NPIX + pix) * 3 + 1];
    const float gz = g[((size_t)b * NPIX + pix) * 3 + 2];
    const float sbase = scale * (t0 + gz);

    // fp16 source: channel c row = 1024 uint4 (16 KB)
    const uint4* rfc = reinterpret_cast<const uint4*>(RF16) + (size_t)b * NC * (NS / 2);
    const uint32_t smem_base = smem_u32(smem);

    auto fill = [&](int c, int slot) {
        const uint4* src = rfc + (size_t)c * (NS / 2);
        uint32_t dst = smem_base + (uint32_t)slot * BUF_BYTES;
        cp_async16(dst + (uint32_t)tid * 16u, src + tid);
        asm volatile("cp.async.commit_group;");
    };

    fill(0, 0); fill(1, 1); fill(2, 2); fill(3, 3);

    float4 accA = make_float4(0.f, 0.f, 0.f, 0.f);
    float4 accB = make_float4(0.f, 0.f, 0.f, 0.f);

    int pairIdx = 0;

    #pragma unroll 1
    for (int c = 0; c < NC; c += 2) {
        if (c + 2 < NC) { asm volatile("cp.async.wait_group 2;"); }
        else            { asm volatile("cp.async.wait_group 0;"); }
        __syncthreads();

        const float paxx = spr[c * 3 + 0], paxy = spr[c * 3 + 1], paxz = spr[c * 3 + 2];
        const float pbxx = spr[c * 3 + 3], pbxy = spr[c * 3 + 4], pbxz = spr[c * 3 + 5];

        float dax = gx - paxx, day = gy - paxy, daz = gz - paxz;
        float dda = fmaf(dax, dax, fmaf(day, day, daz * daz));
        float da; asm("sqrt.approx.f32 %0, %1;" : "=f"(da) : "f"(dda));
        float sa = fmaf(scale, da, sbase);
        sa = fminf(fmaxf(sa, 0.0f), 2047.0f);
        int ia = min((int)sa, NS - 2);
        const float wa = sa - (float)ia, wa0 = 1.0f - wa;

        float dbx = gx - pbxx, dby = gy - pbxy, dbz = gz - pbxz;
        float ddb = fmaf(dbx, dbx, fmaf(dby, dby, dbz * dbz));
        float db; asm("sqrt.approx.f32 %0, %1;" : "=f"(db) : "f"(ddb));
        float sb = fmaf(scale, db, sbase);
        sb = fminf(fmaxf(sb, 0.0f), 2047.0f);
        int ib = min((int)sb, NS - 2);
        const float wb = sb - (float)ib, wb0 = 1.0f - wb;

        const uint2* bufA = reinterpret_cast<const uint2*>(
            reinterpret_cast<const char*>(smem) + (2 * pairIdx)     * BUF_BYTES);
        const uint2* bufB = reinterpret_cast<const uint2*>(
            reinterpret_cast<const char*>(smem) + (2 * pairIdx + 1) * BUF_BYTES);

        if (active) {
            uint2 ra0 = bufA[ia];
            uint2 ra1 = bufA[ia + 1];
            uint2 rb0 = bufB[ib];
            uint2 rb1 = bufB[ib + 1];

            float2 a0lo = __half22float2(*reinterpret_cast<__half2*>(&ra0.x));
            float2 a0hi = __half22float2(*reinterpret_cast<__half2*>(&ra0.y));
            float2 a1lo = __half22float2(*reinterpret_cast<__half2*>(&ra1.x));
            float2 a1hi = __half22float2(*reinterpret_cast<__half2*>(&ra1.y));

            accA.x = fmaf(wa0, a0lo.x, fmaf(wa, a1lo.x, accA.x));
            accA.y = fmaf(wa0, a0lo.y, fmaf(wa, a1lo.y, accA.y));
            accA.z = fmaf(wa0, a0hi.x, fmaf(wa, a1hi.x, accA.z));
            accA.w = fmaf(wa0, a0hi.y, fmaf(wa, a1hi.y, accA.w));

            float2 b0lo = __half22float2(*reinterpret_cast<__half2*>(&rb0.x));
            float2 b0hi = __half22float2(*reinterpret_cast<__half2*>(&rb0.y));
            float2 b1lo = __half22float2(*reinterpret_cast<__half2*>(&rb1.x));
            float2 b1hi = __half22float2(*reinterpret_cast<__half2*>(&rb1.y));

            accB.x = fmaf(wb0, b0lo.x, fmaf(wb, b1lo.x, accB.x));
            accB.y = fmaf(wb0, b0lo.y, fmaf(wb, b1lo.y, accB.y));
            accB.z = fmaf(wb0, b0hi.x, fmaf(wb, b1hi.x, accB.z));
            accB.w = fmaf(wb0, b0hi.y, fmaf(wb, b1hi.y, accB.w));
        }

        if (c + 4 < NC) {
            int fp = pairIdx + 2; if (fp >= 3) fp -= 3;
            fill(c + 4, 2 * fp);
            fill(c + 5, 2 * fp + 1);
        }
        pairIdx = (pairIdx + 1 == 3) ? 0 : pairIdx + 1;
    }

    if (active) {
        float4 r;
        r.x = accA.x + accB.x;
        r.y = accA.y + accB.y;
        r.z = accA.z + accB.z;
        r.w = accA.w + accB.w;
        reinterpret_cast<float4*>(out)[(size_t)b * NPIX + pix0] = r;
    }
}

extern "C" void kernel_launch(void* const* d_in, const int* in_sizes, int n_in,
                              void* d_out, int out_size)
{
    const float* rf = (const float*)d_in[0];
    const float* g  = (const float*)d_in[1];
    const float* pr = (const float*)d_in[2];
    const float* p  = (const float*)d_in[3];
    float* out = (float*)d_out;

    // 2*128*2048 float4 rows / 2 per thread = 262144 threads
    conv_kernel<<<1024, 256>>>(reinterpret_cast<const float4*>(rf));

    cudaFuncSetAttribute(das_kernel, cudaFuncAttributeMaxDynamicSharedMemorySize, SMEM_BYTES);
    das_kernel<<<GRID, THREADS, SMEM_BYTES>>>(g, pr, p, out);
}